// round 11
// baseline (speedup 1.0000x reference)
#include <cuda_runtime.h>
#include <cuda_fp16.h>
#include <cstdint>

#define BB 32
#define LL 512
#define DIN 768
#define HH 16
#define DHH 48
#define DOUTC 768
#define M_TOT (BB*LL)
#define NEGC 1e12f
#define SCALEC 0.14433756729740643f   /* 1/sqrt(48) */

// fp16 scratch (static device globals)
__device__ __half g_q16[(size_t)M_TOT * DOUTC];
__device__ __half g_k16[(size_t)M_TOT * DOUTC];
__device__ __half g_v16[(size_t)M_TOT * DOUTC];

__device__ __forceinline__ unsigned packh(float lo, float hi) {
    __half2 h = __floats2half2_rn(lo, hi);
    return *(unsigned*)&h;
}

__device__ __forceinline__ void mma_f16(float* c, const unsigned* a, const unsigned* b) {
    asm volatile(
        "mma.sync.aligned.m16n8k16.row.col.f32.f16.f16.f32 "
        "{%0,%1,%2,%3}, {%4,%5,%6,%7}, {%8,%9}, {%0,%1,%2,%3};"
        : "+f"(c[0]), "+f"(c[1]), "+f"(c[2]), "+f"(c[3])
        : "r"(a[0]), "r"(a[1]), "r"(a[2]), "r"(a[3]), "r"(b[0]), "r"(b[1]));
}

__device__ __forceinline__ void ldsm4(unsigned* r, uint32_t a) {
    asm volatile("ldmatrix.sync.aligned.m8n8.x4.shared.b16 {%0,%1,%2,%3}, [%4];"
        : "=r"(r[0]), "=r"(r[1]), "=r"(r[2]), "=r"(r[3]) : "r"(a));
}
__device__ __forceinline__ void ldsm4t(unsigned* r, uint32_t a) {
    asm volatile("ldmatrix.sync.aligned.m8n8.x4.trans.shared.b16 {%0,%1,%2,%3}, [%4];"
        : "=r"(r[0]), "=r"(r[1]), "=r"(r[2]), "=r"(r[3]) : "r"(a));
}

__device__ __forceinline__ uint32_t smem_u32(const void* p) {
    uint32_t a;
    asm("{ .reg .u64 t; cvta.to.shared.u64 t, %1; cvt.u32.u64 %0, t; }"
        : "=r"(a) : "l"(p));
    return a;
}

// ---------------------------------------------------------------------------
// Kernel 1: proj GEMM, f32 in -> f16 out, conversion fused into staging.
// ---------------------------------------------------------------------------
#define PA 40
#define PB 136
#define NCHUNK (DIN / 32)
__global__ __launch_bounds__(256, 2) void proj16(
    const float* __restrict__ x0, const float* __restrict__ x1,
    const float* __restrict__ x2,
    const float* __restrict__ w0, const float* __restrict__ w1,
    const float* __restrict__ w2,
    __half* __restrict__ y0, __half* __restrict__ y1, __half* __restrict__ y2) {
    const float* X = (blockIdx.z == 0) ? x0 : (blockIdx.z == 1) ? x1 : x2;
    const float* W = (blockIdx.z == 0) ? w0 : (blockIdx.z == 1) ? w1 : w2;
    __half* Y      = (blockIdx.z == 0) ? y0 : (blockIdx.z == 1) ? y1 : y2;

    __shared__ __align__(16) __half As[2][128 * PA];
    __shared__ __align__(16) __half Bs[2][32 * PB];

    const int t = threadIdx.x, lane = t & 31, w = t >> 5;
    const int g = lane >> 2, tig = lane & 3;
    const int m0 = (w >> 2) * 64, n0 = (w & 3) * 32;
    const int mBase = blockIdx.y * 128, nBase = blockIdx.x * 128;

    const int arow = t >> 1, ah = t & 1;
    const int brow = t >> 3, bn = (t & 7) * 16;
    const float* Xp = X + (size_t)(mBase + arow) * DIN + ah * 16;
    const float* Wp = W + (size_t)brow * DOUTC + nBase + bn;

    const uint32_t aBase = smem_u32(As);
    const uint32_t bBase = smem_u32(Bs);
    const int aLO = (lane & 15) * PA + (lane >> 4) * 8;
    const int bLO = ((lane & 7) + ((lane >> 3) & 1) * 8) * PB + (lane >> 4) * 8;

    float acc[4][4][4];
    #pragma unroll
    for (int i = 0; i < 4; i++)
        #pragma unroll
        for (int j = 0; j < 4; j++)
            #pragma unroll
            for (int c = 0; c < 4; c++) acc[i][j][c] = 0.0f;

    float4 aV[4], bV[4];
    #pragma unroll
    for (int i = 0; i < 4; i++) {
        aV[i] = *(const float4*)(Xp + i * 4);
        bV[i] = *(const float4*)(Wp + i * 4);
    }
    #pragma unroll
    for (int hlf = 0; hlf < 2; hlf++) {
        *(uint4*)&As[0][arow * PA + ah * 16 + hlf * 8] = make_uint4(
            packh(aV[hlf*2].x, aV[hlf*2].y),   packh(aV[hlf*2].z, aV[hlf*2].w),
            packh(aV[hlf*2+1].x, aV[hlf*2+1].y), packh(aV[hlf*2+1].z, aV[hlf*2+1].w));
        *(uint4*)&Bs[0][brow * PB + bn + hlf * 8] = make_uint4(
            packh(bV[hlf*2].x, bV[hlf*2].y),   packh(bV[hlf*2].z, bV[hlf*2].w),
            packh(bV[hlf*2+1].x, bV[hlf*2+1].y), packh(bV[hlf*2+1].z, bV[hlf*2+1].w));
    }
    __syncthreads();

    for (int c = 0; c < NCHUNK; c++) {
        const int cur = c & 1;
        const bool more = (c + 1 < NCHUNK);
        if (more) {
            const int kk = (c + 1) * 32;
            #pragma unroll
            for (int i = 0; i < 4; i++) {
                aV[i] = *(const float4*)(Xp + kk + i * 4);
                bV[i] = *(const float4*)(Wp + (size_t)kk * DOUTC + i * 4);
            }
        }

        const uint32_t aB = aBase + cur * (128 * PA * 2);
        const uint32_t bB = bBase + cur * (32 * PB * 2);
        #pragma unroll
        for (int ks = 0; ks < 2; ks++) {
            const int k0 = ks * 16;
            unsigned a[4][4];
            #pragma unroll
            for (int i = 0; i < 4; i++)
                ldsm4(a[i], aB + (uint32_t)(((m0 + i * 16) * PA) + k0 + aLO) * 2);
            #pragma unroll
            for (int jp = 0; jp < 2; jp++) {
                unsigned b4[4];
                ldsm4t(b4, bB + (uint32_t)((k0 * PB) + n0 + jp * 16 + bLO) * 2);
                #pragma unroll
                for (int i = 0; i < 4; i++) {
                    mma_f16(acc[i][jp * 2 + 0], a[i], b4);
                    mma_f16(acc[i][jp * 2 + 1], a[i], b4 + 2);
                }
            }
        }

        if (more) {
            const int nxt = cur ^ 1;
            #pragma unroll
            for (int hlf = 0; hlf < 2; hlf++) {
                *(uint4*)&As[nxt][arow * PA + ah * 16 + hlf * 8] = make_uint4(
                    packh(aV[hlf*2].x, aV[hlf*2].y),   packh(aV[hlf*2].z, aV[hlf*2].w),
                    packh(aV[hlf*2+1].x, aV[hlf*2+1].y), packh(aV[hlf*2+1].z, aV[hlf*2+1].w));
                *(uint4*)&Bs[nxt][brow * PB + bn + hlf * 8] = make_uint4(
                    packh(bV[hlf*2].x, bV[hlf*2].y),   packh(bV[hlf*2].z, bV[hlf*2].w),
                    packh(bV[hlf*2+1].x, bV[hlf*2+1].y), packh(bV[hlf*2+1].z, bV[hlf*2+1].w));
            }
        }
        __syncthreads();
    }

    #pragma unroll
    for (int i = 0; i < 4; i++) {
        const size_t r1 = (size_t)(mBase + m0 + i * 16 + g);
        const size_t r2 = r1 + 8;
        #pragma unroll
        for (int j = 0; j < 4; j++) {
            const int col = nBase + n0 + j * 8 + tig * 2;
            *(__half2*)(Y + r1 * DOUTC + col) = __floats2half2_rn(acc[i][j][0], acc[i][j][1]);
            *(__half2*)(Y + r2 * DOUTC + col) = __floats2half2_rn(acc[i][j][2], acc[i][j][3]);
        }
    }
}

// ---------------------------------------------------------------------------
// Kernel 2: fused attention, R11: single pass, BALANCED dual-tile k-ownership.
// Warp w owns k-tiles [16w,16w+16) and [496-16w,512-16w) -> ~equal causal work.
// ---------------------------------------------------------------------------
#define RP 56
#define OFF_QS   57344
#define OFF_VS   64512
#define OFF_SSUM 71680
#define OFF_LS   73728
#define SMEM_ATT 73984

__global__ __launch_bounds__(512, 1) void attn_fused(
    const __half* __restrict__ Q16, const __half* __restrict__ K16,
    const __half* __restrict__ V16,
    const int* __restrict__ Qlen, const int* __restrict__ Vlen,
    float* __restrict__ Out) {
    extern __shared__ char smem[];
    __half* KrH = (__half*)smem;
    __half* QsH = (__half*)(smem + OFF_QS);
    __half* VsH = (__half*)(smem + OFF_VS);
    float*  sSum = (float*)(smem + OFF_SSUM);   // [16 warps][32 q]
    float*  lSc  = (float*)(smem + OFF_LS);     // [32] 1/l for current chunk
    const uint32_t krB = smem_u32(smem);
    const uint32_t qsB = krB + OFF_QS;
    const uint32_t vsB = krB + OFF_VS;

    const int b = blockIdx.x >> 4, h = blockIdx.x & 15;
    const int t = threadIdx.x, lane = t & 31, w = t >> 5;
    const int g = lane >> 2, tig = lane & 3;
    const int rowA = w * 16;            // low tile
    const int rowB = 496 - w * 16;      // high tile
    const int vlen = Vlen[b], qlen = Qlen[b];
    const float bias = (vlen == 0) ? NEGC : 0.0f;

    const int aSel = (lane & 15) * RP + (lane >> 4) * 8;
    const int bSel = ((lane & 7) + ((lane >> 4) << 3)) * RP + ((lane >> 3) & 1) * 8;
    const int tSel = ((lane & 7) + (((lane >> 3) & 1) << 3)) * RP + (lane >> 4) * 8;

    const __half* qsrc = Q16 + (size_t)(b * LL) * DOUTC + h * DHH;
    const __half* ksrc = K16 + (size_t)(b * LL) * DOUTC + h * DHH;
    const __half* vsrc = V16 + (size_t)(b * LL) * DOUTC + h * DHH;

    // ---- K resident, natural [k][d] ----
    for (int i = t; i < 3072; i += 512) {
        const int row = i / 6, c4 = i % 6;
        *(uint4*)(KrH + row * RP + c4 * 8) =
            *(const uint4*)(ksrc + (size_t)row * DOUTC + c4 * 8);
    }

    // per-thread staging map (fixed): slot0 = index t, slot1 = t+512 (t<256)
    const int arr0 = t >= 384;
    const int j0 = arr0 ? t - 384 : t;
    const int row0 = j0 / 6, c40 = j0 % 6;
    const __half* src0 = (arr0 ? vsrc : qsrc) + (size_t)row0 * DOUTC + c40 * 8;
    __half* dst0 = (arr0 ? VsH : QsH) + row0 * RP + c40 * 8;
    const int j1 = t + 128;                      // (t+512)-384, always V
    const int row1 = j1 / 6, c41 = j1 % 6;
    const __half* src1 = vsrc + (size_t)row1 * DOUTC + c41 * 8;
    __half* dst1 = VsH + row1 * RP + c41 * 8;

    float oacc[2][6][4];
    #pragma unroll
    for (int mt = 0; mt < 2; mt++)
        #pragma unroll
        for (int nd = 0; nd < 6; nd++)
            #pragma unroll
            for (int c = 0; c < 4; c++) oacc[mt][nd][c] = 0.0f;

    for (int qt = 0; qt < 8; qt++) {
        // prefetch staging before barriers
        const size_t qoff = (size_t)(qt * 64) * DOUTC;
        uint4 p0 = *(const uint4*)(src0 + qoff);
        uint4 p1;
        if (t < 256) p1 = *(const uint4*)(src1 + qoff);
        __syncthreads();   // previous O-mma finished reading Qs/Vs
        *(uint4*)dst0 = p0;
        if (t < 256) *(uint4*)dst1 = p1;
        __syncthreads();

        #pragma unroll
        for (int sub = 0; sub < 2; sub++) {
            const int qc = sub * 32;
            const int qbase = qt * 64 + qc;
            const bool liveA = (rowA <= qbase + 31);
            const bool liveB = (rowB <= qbase + 31);

            float ac[2][4][4];
            float csum[4][2];
            #pragma unroll
            for (int n = 0; n < 4; n++) { csum[n][0] = 0.0f; csum[n][1] = 0.0f; }

            if (liveA || liveB) {
                #pragma unroll
                for (int mt = 0; mt < 2; mt++)
                    #pragma unroll
                    for (int n = 0; n < 4; n++)
                        #pragma unroll
                        for (int c = 0; c < 4; c++) ac[mt][n][c] = 0.0f;
                #pragma unroll
                for (int jd = 0; jd < 3; jd++) {
                    unsigned bq[2][4];
                    ldsm4(bq[0], qsB + (uint32_t)(qc * RP + jd * 16 + bSel) * 2);
                    ldsm4(bq[1], qsB + (uint32_t)((qc + 16) * RP + jd * 16 + bSel) * 2);
                    if (liveA) {
                        unsigned a0[4];
                        ldsm4(a0, krB + (uint32_t)(rowA * RP + jd * 16 + aSel) * 2);
                        mma_f16(ac[0][0], a0, bq[0]);
                        mma_f16(ac[0][1], a0, bq[0] + 2);
                        mma_f16(ac[0][2], a0, bq[1]);
                        mma_f16(ac[0][3], a0, bq[1] + 2);
                    }
                    if (liveB) {
                        unsigned a1[4];
                        ldsm4(a1, krB + (uint32_t)(rowB * RP + jd * 16 + aSel) * 2);
                        mma_f16(ac[1][0], a1, bq[0]);
                        mma_f16(ac[1][1], a1, bq[0] + 2);
                        mma_f16(ac[1][2], a1, bq[1]);
                        mma_f16(ac[1][3], a1, bq[1] + 2);
                    }
                }
                #pragma unroll
                for (int mt = 0; mt < 2; mt++) {
                    if (mt == 0 ? !liveA : !liveB) continue;
                    const int kg0 = (mt == 0 ? rowA : rowB) + g, kg1 = kg0 + 8;
                    #pragma unroll
                    for (int n = 0; n < 4; n++) {
                        const int q0 = qbase + n * 8 + tig * 2;
                        float s0 = ac[mt][n][0] * SCALEC, s1 = ac[mt][n][1] * SCALEC;
                        float s2 = ac[mt][n][2] * SCALEC, s3 = ac[mt][n][3] * SCALEC;
                        if (kg0 >= vlen) { s0 -= NEGC; s1 -= NEGC; }
                        if (kg1 >= vlen) { s2 -= NEGC; s3 -= NEGC; }
                        if (kg0 > q0)     s0 -= NEGC;
                        if (kg0 > q0 + 1) s1 -= NEGC;
                        if (kg1 > q0)     s2 -= NEGC;
                        if (kg1 > q0 + 1) s3 -= NEGC;
                        const float e0 = __expf(s0 + bias), e1 = __expf(s1 + bias);
                        const float e2 = __expf(s2 + bias), e3 = __expf(s3 + bias);
                        ac[mt][n][0] = e0; ac[mt][n][1] = e1;
                        ac[mt][n][2] = e2; ac[mt][n][3] = e3;
                        csum[n][0] += e0 + e2;
                        csum[n][1] += e1 + e3;
                    }
                }
            }
            #pragma unroll
            for (int n = 0; n < 4; n++)
                #pragma unroll
                for (int p = 0; p < 2; p++) {
                    float v = csum[n][p];
                    v += __shfl_xor_sync(0xffffffffu, v, 4);
                    v += __shfl_xor_sync(0xffffffffu, v, 8);
                    v += __shfl_xor_sync(0xffffffffu, v, 16);
                    csum[n][p] = v;
                }
            if (g == 0) {
                #pragma unroll
                for (int n = 0; n < 4; n++)
                    *(float2*)&sSum[w * 32 + n * 8 + tig * 2] =
                        make_float2(csum[n][0], csum[n][1]);
            }
            __syncthreads();
            if (t < 32) {
                float l = 0.0f;
                #pragma unroll
                for (int w2 = 0; w2 < 16; w2++) l += sSum[w2 * 32 + t];
                lSc[t] = 1.0f / l;
            }
            __syncthreads();

            if (liveA || liveB) {
                #pragma unroll
                for (int kc = 0; kc < 2; kc++) {
                    const float2 rrA = *(const float2*)&lSc[kc * 16 + tig * 2];
                    const float2 rrB = *(const float2*)&lSc[kc * 16 + 8 + tig * 2];
                    unsigned aa[2][4];
                    #pragma unroll
                    for (int mt = 0; mt < 2; mt++) {
                        aa[mt][0] = packh(ac[mt][kc * 2][0] * rrA.x, ac[mt][kc * 2][1] * rrA.y);
                        aa[mt][1] = packh(ac[mt][kc * 2][2] * rrA.x, ac[mt][kc * 2][3] * rrA.y);
                        aa[mt][2] = packh(ac[mt][kc * 2 + 1][0] * rrB.x, ac[mt][kc * 2 + 1][1] * rrB.y);
                        aa[mt][3] = packh(ac[mt][kc * 2 + 1][2] * rrB.x, ac[mt][kc * 2 + 1][3] * rrB.y);
                    }
                    #pragma unroll
                    for (int dd = 0; dd < 3; dd++) {
                        unsigned b4[4];
                        ldsm4t(b4, vsB + (uint32_t)((qc + kc * 16) * RP + dd * 16 + tSel) * 2);
                        if (liveA) {
                            mma_f16(oacc[0][dd * 2 + 0], aa[0], b4);
                            mma_f16(oacc[0][dd * 2 + 1], aa[0], b4 + 2);
                        }
                        if (liveB) {
                            mma_f16(oacc[1][dd * 2 + 0], aa[1], b4);
                            mma_f16(oacc[1][dd * 2 + 1], aa[1], b4 + 2);
                        }
                    }
                }
            }
        }
    }

    // epilogue: two owned tiles
    #pragma unroll
    for (int mt = 0; mt < 2; mt++) {
        const int kg0 = (mt == 0 ? rowA : rowB) + g, kg1 = kg0 + 8;
        const float f0 = (kg0 < qlen) ? 1.0f : 0.0f;
        const float f1 = (kg1 < qlen) ? 1.0f : 0.0f;
        #pragma unroll
        for (int nd = 0; nd < 6; nd++) {
            const int col = h * DHH + nd * 8 + tig * 2;
            *(float2*)(Out + (size_t)(b * LL + kg0) * DOUTC + col) =
                make_float2(oacc[mt][nd][0] * f0, oacc[mt][nd][1] * f0);
            *(float2*)(Out + (size_t)(b * LL + kg1) * DOUTC + col) =
                make_float2(oacc[mt][nd][2] * f1, oacc[mt][nd][3] * f1);
        }
    }
}

// ---------------------------------------------------------------------------
extern "C" void kernel_launch(void* const* d_in, const int* in_sizes, int n_in,
                              void* d_out, int out_size) {
    const float* Qseq = (const float*)d_in[0];
    const float* Kseq = (const float*)d_in[1];
    const float* Vseq = (const float*)d_in[2];
    const float* WQ   = (const float*)d_in[3];
    const float* WK   = (const float*)d_in[4];
    const float* WV   = (const float*)d_in[5];
    const int*   Qlen = (const int*)d_in[6];
    const int*   Vlen = (const int*)d_in[7];

    __half *pq, *pk, *pv;
    cudaGetSymbolAddress((void**)&pq, g_q16);
    cudaGetSymbolAddress((void**)&pk, g_k16);
    cudaGetSymbolAddress((void**)&pv, g_v16);

    cudaFuncSetAttribute(attn_fused, cudaFuncAttributeMaxDynamicSharedMemorySize, SMEM_ATT);

    proj16<<<dim3(6, 128, 3), 256>>>(Qseq, Kseq, Vseq, WQ, WK, WV, pq, pk, pv);

    attn_fused<<<BB * HH, 512, SMEM_ATT>>>(pq, pk, pv, Qlen, Vlen, (float*)d_out);
}

// round 12
// speedup vs baseline: 1.2221x; 1.2221x over previous
#include <cuda_runtime.h>
#include <cuda_fp16.h>
#include <cstdint>

#define BB 32
#define LL 512
#define DIN 768
#define HH 16
#define DHH 48
#define DOUTC 768
#define M_TOT (BB*LL)
#define NEGC 1e12f
#define SCALEC 0.14433756729740643f   /* 1/sqrt(48) */

// fp16 scratch (static device globals)
__device__ __half g_x16[3][(size_t)M_TOT * DIN];
__device__ __half g_w16[3][(size_t)DIN * DOUTC];
__device__ __half g_p16[3][(size_t)M_TOT * DOUTC];

__device__ __forceinline__ unsigned packh(float lo, float hi) {
    __half2 h = __floats2half2_rn(lo, hi);
    return *(unsigned*)&h;
}

__device__ __forceinline__ void mma_f16(float* c, const unsigned* a, const unsigned* b) {
    asm volatile(
        "mma.sync.aligned.m16n8k16.row.col.f32.f16.f16.f32 "
        "{%0,%1,%2,%3}, {%4,%5,%6,%7}, {%8,%9}, {%0,%1,%2,%3};"
        : "+f"(c[0]), "+f"(c[1]), "+f"(c[2]), "+f"(c[3])
        : "r"(a[0]), "r"(a[1]), "r"(a[2]), "r"(a[3]), "r"(b[0]), "r"(b[1]));
}

__device__ __forceinline__ void ldsm4(unsigned* r, uint32_t a) {
    asm volatile("ldmatrix.sync.aligned.m8n8.x4.shared.b16 {%0,%1,%2,%3}, [%4];"
        : "=r"(r[0]), "=r"(r[1]), "=r"(r[2]), "=r"(r[3]) : "r"(a));
}
__device__ __forceinline__ void ldsm4t(unsigned* r, uint32_t a) {
    asm volatile("ldmatrix.sync.aligned.m8n8.x4.trans.shared.b16 {%0,%1,%2,%3}, [%4];"
        : "=r"(r[0]), "=r"(r[1]), "=r"(r[2]), "=r"(r[3]) : "r"(a));
}

__device__ __forceinline__ uint32_t smem_u32(const void* p) {
    uint32_t a;
    asm("{ .reg .u64 t; cvta.to.shared.u64 t, %1; cvt.u32.u64 %0, t; }"
        : "=r"(a) : "l"(p));
    return a;
}

__device__ __forceinline__ void cp16(uint32_t dst, const void* src) {
    asm volatile("cp.async.ca.shared.global [%0], [%1], 16;"
                 :: "r"(dst), "l"(src) : "memory");
}
__device__ __forceinline__ void cp_commit() {
    asm volatile("cp.async.commit_group;" ::: "memory");
}
__device__ __forceinline__ void cp_wait0() {
    asm volatile("cp.async.wait_group 0;" ::: "memory");
}

// ---------------------------------------------------------------------------
// Prep: f32 -> f16 flat convert (3 inputs selected by blockIdx.y)
// ---------------------------------------------------------------------------
__global__ void conv_f2h(const float* __restrict__ s0, const float* __restrict__ s1,
                         const float* __restrict__ s2, __half* __restrict__ dBase,
                         size_t dStride, int n4) {
    const float* s = (blockIdx.y == 0) ? s0 : (blockIdx.y == 1) ? s1 : s2;
    __half* d = dBase + blockIdx.y * dStride;
    for (int i = blockIdx.x * blockDim.x + threadIdx.x; i < n4;
         i += gridDim.x * blockDim.x) {
        float4 v = ((const float4*)s)[i];
        uint2 o = make_uint2(packh(v.x, v.y), packh(v.z, v.w));
        ((uint2*)d)[i] = o;
    }
}

// ---------------------------------------------------------------------------
// Kernel 1: FP16 proj GEMM, ldmatrix + cp.async double-buffered staging.
// ---------------------------------------------------------------------------
#define PA 40
#define PB 136
#define NCHUNK (DIN / 32)
__global__ __launch_bounds__(256, 2) void proj16(
    const __half* __restrict__ Xall, const __half* __restrict__ Wall,
    __half* __restrict__ Yall) {
    const __half* X = Xall + (size_t)blockIdx.z * M_TOT * DIN;
    const __half* W = Wall + (size_t)blockIdx.z * DIN * DOUTC;
    __half* Y       = Yall + (size_t)blockIdx.z * M_TOT * DOUTC;

    __shared__ __align__(16) __half As[2][128 * PA];
    __shared__ __align__(16) __half Bs[2][32 * PB];

    const int t = threadIdx.x, lane = t & 31, w = t >> 5;
    const int g = lane >> 2, tig = lane & 3;
    const int m0 = (w >> 2) * 64, n0 = (w & 3) * 32;
    const int mBase = blockIdx.y * 128, nBase = blockIdx.x * 128;

    const int arow = t >> 1, ah = t & 1;
    const int brow = t >> 3, bn = (t & 7) * 16;
    const __half* Xp = X + (size_t)(mBase + arow) * DIN + ah * 16;
    const __half* Wp = W + (size_t)brow * DOUTC + nBase + bn;

    const uint32_t aBase = smem_u32(As);
    const uint32_t bBase = smem_u32(Bs);
    const uint32_t aDst = aBase + (uint32_t)(arow * PA + ah * 16) * 2;
    const uint32_t bDst = bBase + (uint32_t)(brow * PB + bn) * 2;
    const int aLO = (lane & 15) * PA + (lane >> 4) * 8;
    const int bLO = ((lane & 7) + ((lane >> 3) & 1) * 8) * PB + (lane >> 4) * 8;

    float acc[4][4][4];
    #pragma unroll
    for (int i = 0; i < 4; i++)
        #pragma unroll
        for (int j = 0; j < 4; j++)
            #pragma unroll
            for (int c = 0; c < 4; c++) acc[i][j][c] = 0.0f;

    // stage chunk 0 -> buf 0
    cp16(aDst, Xp);
    cp16(aDst + 16, Xp + 8);
    cp16(bDst, Wp);
    cp16(bDst + 16, Wp + 8);
    cp_commit();
    cp_wait0();
    __syncthreads();

    for (int c = 0; c < NCHUNK; c++) {
        const int cur = c & 1;
        const bool more = (c + 1 < NCHUNK);
        if (more) {
            const int kk = (c + 1) * 32;
            const int nxt = cur ^ 1;
            const uint32_t aD = aDst + (uint32_t)(nxt ? 128 * PA * 2 : 0) - (uint32_t)(cur ? 0 : 0);
            const uint32_t aD2 = aBase + (uint32_t)(nxt * 128 * PA + arow * PA + ah * 16) * 2;
            const uint32_t bD2 = bBase + (uint32_t)(nxt * 32 * PB + brow * PB + bn) * 2;
            (void)aD;
            cp16(aD2, Xp + kk);
            cp16(aD2 + 16, Xp + kk + 8);
            cp16(bD2, Wp + (size_t)kk * DOUTC);
            cp16(bD2 + 16, Wp + (size_t)kk * DOUTC + 8);
            cp_commit();
        }

        const uint32_t aB = aBase + cur * (128 * PA * 2);
        const uint32_t bB = bBase + cur * (32 * PB * 2);
        #pragma unroll
        for (int ks = 0; ks < 2; ks++) {
            const int k0 = ks * 16;
            unsigned a[4][4];
            #pragma unroll
            for (int i = 0; i < 4; i++)
                ldsm4(a[i], aB + (uint32_t)(((m0 + i * 16) * PA) + k0 + aLO) * 2);
            #pragma unroll
            for (int jp = 0; jp < 2; jp++) {
                unsigned b4[4];
                ldsm4t(b4, bB + (uint32_t)((k0 * PB) + n0 + jp * 16 + bLO) * 2);
                #pragma unroll
                for (int i = 0; i < 4; i++) {
                    mma_f16(acc[i][jp * 2 + 0], a[i], b4);
                    mma_f16(acc[i][jp * 2 + 1], a[i], b4 + 2);
                }
            }
        }

        if (more) cp_wait0();
        __syncthreads();
    }

    #pragma unroll
    for (int i = 0; i < 4; i++) {
        const size_t r1 = (size_t)(mBase + m0 + i * 16 + g);
        const size_t r2 = r1 + 8;
        #pragma unroll
        for (int j = 0; j < 4; j++) {
            const int col = nBase + n0 + j * 8 + tig * 2;
            *(__half2*)(Y + r1 * DOUTC + col) = __floats2half2_rn(acc[i][j][0], acc[i][j][1]);
            *(__half2*)(Y + r2 * DOUTC + col) = __floats2half2_rn(acc[i][j][2], acc[i][j][3]);
        }
    }
}

// ---------------------------------------------------------------------------
// Kernel 2: fused attention, single pass, balanced dual-tile k-ownership
// (validated R11).
// ---------------------------------------------------------------------------
#define RP 56
#define OFF_QS   57344
#define OFF_VS   64512
#define OFF_SSUM 71680
#define OFF_LS   73728
#define SMEM_ATT 73984

__global__ __launch_bounds__(512, 1) void attn_fused(
    const __half* __restrict__ P16,
    const int* __restrict__ Qlen, const int* __restrict__ Vlen,
    float* __restrict__ Out) {
    extern __shared__ char smem[];
    __half* KrH = (__half*)smem;
    __half* QsH = (__half*)(smem + OFF_QS);
    __half* VsH = (__half*)(smem + OFF_VS);
    float*  sSum = (float*)(smem + OFF_SSUM);
    float*  lSc  = (float*)(smem + OFF_LS);
    const uint32_t krB = smem_u32(smem);
    const uint32_t qsB = krB + OFF_QS;
    const uint32_t vsB = krB + OFF_VS;

    const int b = blockIdx.x >> 4, h = blockIdx.x & 15;
    const int t = threadIdx.x, lane = t & 31, w = t >> 5;
    const int g = lane >> 2, tig = lane & 3;
    const int rowA = w * 16;
    const int rowB = 496 - w * 16;
    const int vlen = Vlen[b], qlen = Qlen[b];
    const float bias = (vlen == 0) ? NEGC : 0.0f;

    const int aSel = (lane & 15) * RP + (lane >> 4) * 8;
    const int bSel = ((lane & 7) + ((lane >> 4) << 3)) * RP + ((lane >> 3) & 1) * 8;
    const int tSel = ((lane & 7) + (((lane >> 3) & 1) << 3)) * RP + (lane >> 4) * 8;

    const __half* qsrc = P16 + (size_t)(b * LL) * DOUTC + h * DHH;
    const __half* ksrc = qsrc + (size_t)M_TOT * DOUTC;
    const __half* vsrc = ksrc + (size_t)M_TOT * DOUTC;

    for (int i = t; i < 3072; i += 512) {
        const int row = i / 6, c4 = i % 6;
        *(uint4*)(KrH + row * RP + c4 * 8) =
            *(const uint4*)(ksrc + (size_t)row * DOUTC + c4 * 8);
    }

    const int arr0 = t >= 384;
    const int j0 = arr0 ? t - 384 : t;
    const int row0 = j0 / 6, c40 = j0 % 6;
    const __half* src0 = (arr0 ? vsrc : qsrc) + (size_t)row0 * DOUTC + c40 * 8;
    __half* dst0 = (arr0 ? VsH : QsH) + row0 * RP + c40 * 8;
    const int j1 = t + 128;
    const int row1 = j1 / 6, c41 = j1 % 6;
    const __half* src1 = vsrc + (size_t)row1 * DOUTC + c41 * 8;
    __half* dst1 = VsH + row1 * RP + c41 * 8;

    float oacc[2][6][4];
    #pragma unroll
    for (int mt = 0; mt < 2; mt++)
        #pragma unroll
        for (int nd = 0; nd < 6; nd++)
            #pragma unroll
            for (int c = 0; c < 4; c++) oacc[mt][nd][c] = 0.0f;

    for (int qt = 0; qt < 8; qt++) {
        const size_t qoff = (size_t)(qt * 64) * DOUTC;
        uint4 p0 = *(const uint4*)(src0 + qoff);
        uint4 p1;
        if (t < 256) p1 = *(const uint4*)(src1 + qoff);
        __syncthreads();
        *(uint4*)dst0 = p0;
        if (t < 256) *(uint4*)dst1 = p1;
        __syncthreads();

        #pragma unroll
        for (int sub = 0; sub < 2; sub++) {
            const int qc = sub * 32;
            const int qbase = qt * 64 + qc;
            const bool liveA = (rowA <= qbase + 31);
            const bool liveB = (rowB <= qbase + 31);

            float ac[2][4][4];
            float csum[4][2];
            #pragma unroll
            for (int n = 0; n < 4; n++) { csum[n][0] = 0.0f; csum[n][1] = 0.0f; }

            if (liveA || liveB) {
                #pragma unroll
                for (int mt = 0; mt < 2; mt++)
                    #pragma unroll
                    for (int n = 0; n < 4; n++)
                        #pragma unroll
                        for (int c = 0; c < 4; c++) ac[mt][n][c] = 0.0f;
                #pragma unroll
                for (int jd = 0; jd < 3; jd++) {
                    unsigned bq[2][4];
                    ldsm4(bq[0], qsB + (uint32_t)(qc * RP + jd * 16 + bSel) * 2);
                    ldsm4(bq[1], qsB + (uint32_t)((qc + 16) * RP + jd * 16 + bSel) * 2);
                    if (liveA) {
                        unsigned a0[4];
                        ldsm4(a0, krB + (uint32_t)(rowA * RP + jd * 16 + aSel) * 2);
                        mma_f16(ac[0][0], a0, bq[0]);
                        mma_f16(ac[0][1], a0, bq[0] + 2);
                        mma_f16(ac[0][2], a0, bq[1]);
                        mma_f16(ac[0][3], a0, bq[1] + 2);
                    }
                    if (liveB) {
                        unsigned a1[4];
                        ldsm4(a1, krB + (uint32_t)(rowB * RP + jd * 16 + aSel) * 2);
                        mma_f16(ac[1][0], a1, bq[0]);
                        mma_f16(ac[1][1], a1, bq[0] + 2);
                        mma_f16(ac[1][2], a1, bq[1]);
                        mma_f16(ac[1][3], a1, bq[1] + 2);
                    }
                }
                #pragma unroll
                for (int mt = 0; mt < 2; mt++) {
                    if (mt == 0 ? !liveA : !liveB) continue;
                    const int kg0 = (mt == 0 ? rowA : rowB) + g, kg1 = kg0 + 8;
                    #pragma unroll
                    for (int n = 0; n < 4; n++) {
                        const int q0 = qbase + n * 8 + tig * 2;
                        float s0 = ac[mt][n][0] * SCALEC, s1 = ac[mt][n][1] * SCALEC;
                        float s2 = ac[mt][n][2] * SCALEC, s3 = ac[mt][n][3] * SCALEC;
                        if (kg0 >= vlen) { s0 -= NEGC; s1 -= NEGC; }
                        if (kg1 >= vlen) { s2 -= NEGC; s3 -= NEGC; }
                        if (kg0 > q0)     s0 -= NEGC;
                        if (kg0 > q0 + 1) s1 -= NEGC;
                        if (kg1 > q0)     s2 -= NEGC;
                        if (kg1 > q0 + 1) s3 -= NEGC;
                        const float e0 = __expf(s0 + bias), e1 = __expf(s1 + bias);
                        const float e2 = __expf(s2 + bias), e3 = __expf(s3 + bias);
                        ac[mt][n][0] = e0; ac[mt][n][1] = e1;
                        ac[mt][n][2] = e2; ac[mt][n][3] = e3;
                        csum[n][0] += e0 + e2;
                        csum[n][1] += e1 + e3;
                    }
                }
            }
            #pragma unroll
            for (int n = 0; n < 4; n++)
                #pragma unroll
                for (int p = 0; p < 2; p++) {
                    float v = csum[n][p];
                    v += __shfl_xor_sync(0xffffffffu, v, 4);
                    v += __shfl_xor_sync(0xffffffffu, v, 8);
                    v += __shfl_xor_sync(0xffffffffu, v, 16);
                    csum[n][p] = v;
                }
            if (g == 0) {
                #pragma unroll
                for (int n = 0; n < 4; n++)
                    *(float2*)&sSum[w * 32 + n * 8 + tig * 2] =
                        make_float2(csum[n][0], csum[n][1]);
            }
            __syncthreads();
            if (t < 32) {
                float l = 0.0f;
                #pragma unroll
                for (int w2 = 0; w2 < 16; w2++) l += sSum[w2 * 32 + t];
                lSc[t] = 1.0f / l;
            }
            __syncthreads();

            if (liveA || liveB) {
                #pragma unroll
                for (int kc = 0; kc < 2; kc++) {
                    const float2 rrA = *(const float2*)&lSc[kc * 16 + tig * 2];
                    const float2 rrB = *(const float2*)&lSc[kc * 16 + 8 + tig * 2];
                    unsigned aa[2][4];
                    #pragma unroll
                    for (int mt = 0; mt < 2; mt++) {
                        aa[mt][0] = packh(ac[mt][kc * 2][0] * rrA.x, ac[mt][kc * 2][1] * rrA.y);
                        aa[mt][1] = packh(ac[mt][kc * 2][2] * rrA.x, ac[mt][kc * 2][3] * rrA.y);
                        aa[mt][2] = packh(ac[mt][kc * 2 + 1][0] * rrB.x, ac[mt][kc * 2 + 1][1] * rrB.y);
                        aa[mt][3] = packh(ac[mt][kc * 2 + 1][2] * rrB.x, ac[mt][kc * 2 + 1][3] * rrB.y);
                    }
                    #pragma unroll
                    for (int dd = 0; dd < 3; dd++) {
                        unsigned b4[4];
                        ldsm4t(b4, vsB + (uint32_t)((qc + kc * 16) * RP + dd * 16 + tSel) * 2);
                        if (liveA) {
                            mma_f16(oacc[0][dd * 2 + 0], aa[0], b4);
                            mma_f16(oacc[0][dd * 2 + 1], aa[0], b4 + 2);
                        }
                        if (liveB) {
                            mma_f16(oacc[1][dd * 2 + 0], aa[1], b4);
                            mma_f16(oacc[1][dd * 2 + 1], aa[1], b4 + 2);
                        }
                    }
                }
            }
        }
    }

    #pragma unroll
    for (int mt = 0; mt < 2; mt++) {
        const int kg0 = (mt == 0 ? rowA : rowB) + g, kg1 = kg0 + 8;
        const float f0 = (kg0 < qlen) ? 1.0f : 0.0f;
        const float f1 = (kg1 < qlen) ? 1.0f : 0.0f;
        #pragma unroll
        for (int nd = 0; nd < 6; nd++) {
            const int col = h * DHH + nd * 8 + tig * 2;
            *(float2*)(Out + (size_t)(b * LL + kg0) * DOUTC + col) =
                make_float2(oacc[mt][nd][0] * f0, oacc[mt][nd][1] * f0);
            *(float2*)(Out + (size_t)(b * LL + kg1) * DOUTC + col) =
                make_float2(oacc[mt][nd][2] * f1, oacc[mt][nd][3] * f1);
        }
    }
}

// ---------------------------------------------------------------------------
extern "C" void kernel_launch(void* const* d_in, const int* in_sizes, int n_in,
                              void* d_out, int out_size) {
    const float* Qseq = (const float*)d_in[0];
    const float* Kseq = (const float*)d_in[1];
    const float* Vseq = (const float*)d_in[2];
    const float* WQ   = (const float*)d_in[3];
    const float* WK   = (const float*)d_in[4];
    const float* WV   = (const float*)d_in[5];
    const int*   Qlen = (const int*)d_in[6];
    const int*   Vlen = (const int*)d_in[7];

    __half *x16, *w16, *p16;
    cudaGetSymbolAddress((void**)&x16, g_x16);
    cudaGetSymbolAddress((void**)&w16, g_w16);
    cudaGetSymbolAddress((void**)&p16, g_p16);

    cudaFuncSetAttribute(attn_fused, cudaFuncAttributeMaxDynamicSharedMemorySize, SMEM_ATT);

    conv_f2h<<<dim3(2048, 3), 256>>>(Qseq, Kseq, Vseq, x16,
                                     (size_t)M_TOT * DIN, M_TOT * DIN / 4);
    conv_f2h<<<dim3(576, 3), 256>>>(WQ, WK, WV, w16,
                                    (size_t)DIN * DOUTC, DIN * DOUTC / 4);

    proj16<<<dim3(6, 128, 3), 256>>>(x16, w16, p16);

    attn_fused<<<BB * HH, 512, SMEM_ATT>>>(p16, Qlen, Vlen, (float*)d_out);
}

// round 13
// speedup vs baseline: 1.2245x; 1.0019x over previous
#include <cuda_runtime.h>
#include <cuda_fp16.h>
#include <cstdint>

#define BB 32
#define LL 512
#define DIN 768
#define HH 16
#define DHH 48
#define DOUTC 768
#define M_TOT (BB*LL)
#define NEGC 1e12f
#define SCALEC 0.14433756729740643f     /* 1/sqrt(48) */
#define C2E 0.20823031078486745f        /* SCALEC * log2(e) */
#define NEG2 1.4426950408889634e12f     /* NEGC * log2(e) */

// fp16 scratch (static device globals)
__device__ __half g_x16[3][(size_t)M_TOT * DIN];
__device__ __half g_w16[3][(size_t)DIN * DOUTC];
__device__ __half g_p16[3][(size_t)M_TOT * DOUTC];

__device__ __forceinline__ unsigned packh(float lo, float hi) {
    __half2 h = __floats2half2_rn(lo, hi);
    return *(unsigned*)&h;
}
__device__ __forceinline__ unsigned hmul2u(unsigned a, unsigned b) {
    __half2 r = __hmul2(*(__half2*)&a, *(__half2*)&b);
    return *(unsigned*)&r;
}
__device__ __forceinline__ float fex2(float x) {
    float r;
    asm("ex2.approx.f32 %0, %1;" : "=f"(r) : "f"(x));
    return r;
}

__device__ __forceinline__ void mma_f16(float* c, const unsigned* a, const unsigned* b) {
    asm volatile(
        "mma.sync.aligned.m16n8k16.row.col.f32.f16.f16.f32 "
        "{%0,%1,%2,%3}, {%4,%5,%6,%7}, {%8,%9}, {%0,%1,%2,%3};"
        : "+f"(c[0]), "+f"(c[1]), "+f"(c[2]), "+f"(c[3])
        : "r"(a[0]), "r"(a[1]), "r"(a[2]), "r"(a[3]), "r"(b[0]), "r"(b[1]));
}

__device__ __forceinline__ void ldsm4(unsigned* r, uint32_t a) {
    asm volatile("ldmatrix.sync.aligned.m8n8.x4.shared.b16 {%0,%1,%2,%3}, [%4];"
        : "=r"(r[0]), "=r"(r[1]), "=r"(r[2]), "=r"(r[3]) : "r"(a));
}
__device__ __forceinline__ void ldsm4t(unsigned* r, uint32_t a) {
    asm volatile("ldmatrix.sync.aligned.m8n8.x4.trans.shared.b16 {%0,%1,%2,%3}, [%4];"
        : "=r"(r[0]), "=r"(r[1]), "=r"(r[2]), "=r"(r[3]) : "r"(a));
}

__device__ __forceinline__ uint32_t smem_u32(const void* p) {
    uint32_t a;
    asm("{ .reg .u64 t; cvta.to.shared.u64 t, %1; cvt.u32.u64 %0, t; }"
        : "=r"(a) : "l"(p));
    return a;
}

__device__ __forceinline__ void cp16(uint32_t dst, const void* src) {
    asm volatile("cp.async.ca.shared.global [%0], [%1], 16;"
                 :: "r"(dst), "l"(src) : "memory");
}
__device__ __forceinline__ void cp_commit() {
    asm volatile("cp.async.commit_group;" ::: "memory");
}
__device__ __forceinline__ void cp_wait0() {
    asm volatile("cp.async.wait_group 0;" ::: "memory");
}

// ---------------------------------------------------------------------------
// Prep: f32 -> f16 flat convert
// ---------------------------------------------------------------------------
__global__ void conv_f2h(const float* __restrict__ s0, const float* __restrict__ s1,
                         const float* __restrict__ s2, __half* __restrict__ dBase,
                         size_t dStride, int n4) {
    const float* s = (blockIdx.y == 0) ? s0 : (blockIdx.y == 1) ? s1 : s2;
    __half* d = dBase + blockIdx.y * dStride;
    for (int i = blockIdx.x * blockDim.x + threadIdx.x; i < n4;
         i += gridDim.x * blockDim.x) {
        float4 v = ((const float4*)s)[i];
        uint2 o = make_uint2(packh(v.x, v.y), packh(v.z, v.w));
        ((uint2*)d)[i] = o;
    }
}

// ---------------------------------------------------------------------------
// Kernel 1: FP16 proj GEMM, ldmatrix + cp.async (validated R12).
// ---------------------------------------------------------------------------
#define PA 40
#define PB 136
#define NCHUNK (DIN / 32)
__global__ __launch_bounds__(256, 2) void proj16(
    const __half* __restrict__ Xall, const __half* __restrict__ Wall,
    __half* __restrict__ Yall) {
    const __half* X = Xall + (size_t)blockIdx.z * M_TOT * DIN;
    const __half* W = Wall + (size_t)blockIdx.z * DIN * DOUTC;
    __half* Y       = Yall + (size_t)blockIdx.z * M_TOT * DOUTC;

    __shared__ __align__(16) __half As[2][128 * PA];
    __shared__ __align__(16) __half Bs[2][32 * PB];

    const int t = threadIdx.x, lane = t & 31, w = t >> 5;
    const int g = lane >> 2, tig = lane & 3;
    const int m0 = (w >> 2) * 64, n0 = (w & 3) * 32;
    const int mBase = blockIdx.y * 128, nBase = blockIdx.x * 128;

    const int arow = t >> 1, ah = t & 1;
    const int brow = t >> 3, bn = (t & 7) * 16;
    const __half* Xp = X + (size_t)(mBase + arow) * DIN + ah * 16;
    const __half* Wp = W + (size_t)brow * DOUTC + nBase + bn;

    const uint32_t aBase = smem_u32(As);
    const uint32_t bBase = smem_u32(Bs);
    const uint32_t aDst = aBase + (uint32_t)(arow * PA + ah * 16) * 2;
    const uint32_t bDst = bBase + (uint32_t)(brow * PB + bn) * 2;
    const int aLO = (lane & 15) * PA + (lane >> 4) * 8;
    const int bLO = ((lane & 7) + ((lane >> 3) & 1) * 8) * PB + (lane >> 4) * 8;

    float acc[4][4][4];
    #pragma unroll
    for (int i = 0; i < 4; i++)
        #pragma unroll
        for (int j = 0; j < 4; j++)
            #pragma unroll
            for (int c = 0; c < 4; c++) acc[i][j][c] = 0.0f;

    cp16(aDst, Xp);
    cp16(aDst + 16, Xp + 8);
    cp16(bDst, Wp);
    cp16(bDst + 16, Wp + 8);
    cp_commit();
    cp_wait0();
    __syncthreads();

    for (int c = 0; c < NCHUNK; c++) {
        const int cur = c & 1;
        const bool more = (c + 1 < NCHUNK);
        if (more) {
            const int kk = (c + 1) * 32;
            const int nxt = cur ^ 1;
            const uint32_t aD2 = aBase + (uint32_t)(nxt * 128 * PA + arow * PA + ah * 16) * 2;
            const uint32_t bD2 = bBase + (uint32_t)(nxt * 32 * PB + brow * PB + bn) * 2;
            cp16(aD2, Xp + kk);
            cp16(aD2 + 16, Xp + kk + 8);
            cp16(bD2, Wp + (size_t)kk * DOUTC);
            cp16(bD2 + 16, Wp + (size_t)kk * DOUTC + 8);
            cp_commit();
        }

        const uint32_t aB = aBase + cur * (128 * PA * 2);
        const uint32_t bB = bBase + cur * (32 * PB * 2);
        #pragma unroll
        for (int ks = 0; ks < 2; ks++) {
            const int k0 = ks * 16;
            unsigned a[4][4];
            #pragma unroll
            for (int i = 0; i < 4; i++)
                ldsm4(a[i], aB + (uint32_t)(((m0 + i * 16) * PA) + k0 + aLO) * 2);
            #pragma unroll
            for (int jp = 0; jp < 2; jp++) {
                unsigned b4[4];
                ldsm4t(b4, bB + (uint32_t)((k0 * PB) + n0 + jp * 16 + bLO) * 2);
                #pragma unroll
                for (int i = 0; i < 4; i++) {
                    mma_f16(acc[i][jp * 2 + 0], a[i], b4);
                    mma_f16(acc[i][jp * 2 + 1], a[i], b4 + 2);
                }
            }
        }

        if (more) cp_wait0();
        __syncthreads();
    }

    #pragma unroll
    for (int i = 0; i < 4; i++) {
        const size_t r1 = (size_t)(mBase + m0 + i * 16 + g);
        const size_t r2 = r1 + 8;
        #pragma unroll
        for (int j = 0; j < 4; j++) {
            const int col = nBase + n0 + j * 8 + tig * 2;
            *(__half2*)(Y + r1 * DOUTC + col) = __floats2half2_rn(acc[i][j][0], acc[i][j][1]);
            *(__half2*)(Y + r2 * DOUTC + col) = __floats2half2_rn(acc[i][j][2], acc[i][j][3]);
        }
    }
}

// ---------------------------------------------------------------------------
// Kernel 2: fused attention R13: merged-barrier single pass.
// Per 64-q chunk: S+exp (both 32-q subs, packed to half2) -> 1 reduce barrier
// -> lS -> 1 barrier -> O-mma both subs (1/l applied via __hmul2).
// ---------------------------------------------------------------------------
#define RP 56
#define OFF_QS   57344
#define OFF_VS   64512
#define OFF_SSUM 71680
#define OFF_LS   75776
#define SMEM_ATT 76032

__global__ __launch_bounds__(512, 1) void attn_fused(
    const __half* __restrict__ P16,
    const int* __restrict__ Qlen, const int* __restrict__ Vlen,
    float* __restrict__ Out) {
    extern __shared__ char smem[];
    __half* KrH = (__half*)smem;
    __half* QsH = (__half*)(smem + OFF_QS);
    __half* VsH = (__half*)(smem + OFF_VS);
    float*  sSum = (float*)(smem + OFF_SSUM);   // [16 warps][64 q]
    float*  lSc  = (float*)(smem + OFF_LS);     // [64] 1/l for current chunk
    const uint32_t krB = smem_u32(smem);
    const uint32_t qsB = krB + OFF_QS;
    const uint32_t vsB = krB + OFF_VS;

    const int b = blockIdx.x >> 4, h = blockIdx.x & 15;
    const int t = threadIdx.x, lane = t & 31, w = t >> 5;
    const int g = lane >> 2, tig = lane & 3;
    const int rowA = w * 16;
    const int rowB = 496 - w * 16;
    const int vlen = Vlen[b], qlen = Qlen[b];
    const float bias2 = (vlen == 0) ? NEG2 : 0.0f;

    const int aSel = (lane & 15) * RP + (lane >> 4) * 8;
    const int bSel = ((lane & 7) + ((lane >> 4) << 3)) * RP + ((lane >> 3) & 1) * 8;
    const int tSel = ((lane & 7) + (((lane >> 3) & 1) << 3)) * RP + (lane >> 4) * 8;

    const __half* qsrc = P16 + (size_t)(b * LL) * DOUTC + h * DHH;
    const __half* ksrc = qsrc + (size_t)M_TOT * DOUTC;
    const __half* vsrc = ksrc + (size_t)M_TOT * DOUTC;

    for (int i = t; i < 3072; i += 512) {
        const int row = i / 6, c4 = i % 6;
        *(uint4*)(KrH + row * RP + c4 * 8) =
            *(const uint4*)(ksrc + (size_t)row * DOUTC + c4 * 8);
    }

    const int arr0 = t >= 384;
    const int j0 = arr0 ? t - 384 : t;
    const int row0 = j0 / 6, c40 = j0 % 6;
    const __half* src0 = (arr0 ? vsrc : qsrc) + (size_t)row0 * DOUTC + c40 * 8;
    __half* dst0 = (arr0 ? VsH : QsH) + row0 * RP + c40 * 8;
    const int j1 = t + 128;
    const int row1 = j1 / 6, c41 = j1 % 6;
    const __half* src1 = vsrc + (size_t)row1 * DOUTC + c41 * 8;
    __half* dst1 = VsH + row1 * RP + c41 * 8;

    float oacc[2][6][4];
    #pragma unroll
    for (int mt = 0; mt < 2; mt++)
        #pragma unroll
        for (int nd = 0; nd < 6; nd++)
            #pragma unroll
            for (int c = 0; c < 4; c++) oacc[mt][nd][c] = 0.0f;

    unsigned aaS[2][2][2][4];   // [sub][mt][kc][frag]

    for (int qt = 0; qt < 8; qt++) {
        const size_t qoff = (size_t)(qt * 64) * DOUTC;
        uint4 p0 = *(const uint4*)(src0 + qoff);
        uint4 p1;
        if (t < 256) p1 = *(const uint4*)(src1 + qoff);
        __syncthreads();
        *(uint4*)dst0 = p0;
        if (t < 256) *(uint4*)dst1 = p1;
        __syncthreads();

        // ---------- S + exp for both subs, packed to half2 ----------
        #pragma unroll
        for (int sub = 0; sub < 2; sub++) {
            const int qc = sub * 32;
            const int qbase = qt * 64 + qc;
            const bool liveA = (rowA <= qbase + 31);
            const bool liveB = (rowB <= qbase + 31);

            float csum[4][2];
            #pragma unroll
            for (int n = 0; n < 4; n++) { csum[n][0] = 0.0f; csum[n][1] = 0.0f; }

            if (liveA || liveB) {
                float ac[2][4][4];
                #pragma unroll
                for (int mt = 0; mt < 2; mt++)
                    #pragma unroll
                    for (int n = 0; n < 4; n++)
                        #pragma unroll
                        for (int c = 0; c < 4; c++) ac[mt][n][c] = 0.0f;
                #pragma unroll
                for (int jd = 0; jd < 3; jd++) {
                    unsigned bq[2][4];
                    ldsm4(bq[0], qsB + (uint32_t)(qc * RP + jd * 16 + bSel) * 2);
                    ldsm4(bq[1], qsB + (uint32_t)((qc + 16) * RP + jd * 16 + bSel) * 2);
                    if (liveA) {
                        unsigned a0[4];
                        ldsm4(a0, krB + (uint32_t)(rowA * RP + jd * 16 + aSel) * 2);
                        mma_f16(ac[0][0], a0, bq[0]);
                        mma_f16(ac[0][1], a0, bq[0] + 2);
                        mma_f16(ac[0][2], a0, bq[1]);
                        mma_f16(ac[0][3], a0, bq[1] + 2);
                    }
                    if (liveB) {
                        unsigned a1[4];
                        ldsm4(a1, krB + (uint32_t)(rowB * RP + jd * 16 + aSel) * 2);
                        mma_f16(ac[1][0], a1, bq[0]);
                        mma_f16(ac[1][1], a1, bq[0] + 2);
                        mma_f16(ac[1][2], a1, bq[1]);
                        mma_f16(ac[1][3], a1, bq[1] + 2);
                    }
                }
                #pragma unroll
                for (int mt = 0; mt < 2; mt++) {
                    if (mt == 0 ? !liveA : !liveB) continue;
                    const int rowX = (mt == 0) ? rowA : rowB;
                    const int kg0 = rowX + g, kg1 = kg0 + 8;
                    const bool nomask = (rowX + 15 <= qbase) && (rowX + 15 < vlen);
                    if (nomask) {
                        #pragma unroll
                        for (int n = 0; n < 4; n++) {
                            const float e0 = fex2(ac[mt][n][0] * C2E);
                            const float e1 = fex2(ac[mt][n][1] * C2E);
                            const float e2 = fex2(ac[mt][n][2] * C2E);
                            const float e3 = fex2(ac[mt][n][3] * C2E);
                            csum[n][0] += e0 + e2;
                            csum[n][1] += e1 + e3;
                            aaS[sub][mt][n >> 1][(n & 1) * 2 + 0] = packh(e0, e1);
                            aaS[sub][mt][n >> 1][(n & 1) * 2 + 1] = packh(e2, e3);
                        }
                    } else {
                        const float v0 = (kg0 >= vlen) ? NEG2 : 0.0f;
                        const float v1 = (kg1 >= vlen) ? NEG2 : 0.0f;
                        #pragma unroll
                        for (int n = 0; n < 4; n++) {
                            const int q0 = qbase + n * 8 + tig * 2;
                            float s0 = ac[mt][n][0] * C2E - v0;
                            float s1 = ac[mt][n][1] * C2E - v0;
                            float s2 = ac[mt][n][2] * C2E - v1;
                            float s3 = ac[mt][n][3] * C2E - v1;
                            if (kg0 > q0)     s0 -= NEG2;
                            if (kg0 > q0 + 1) s1 -= NEG2;
                            if (kg1 > q0)     s2 -= NEG2;
                            if (kg1 > q0 + 1) s3 -= NEG2;
                            const float e0 = fex2(s0 + bias2), e1 = fex2(s1 + bias2);
                            const float e2 = fex2(s2 + bias2), e3 = fex2(s3 + bias2);
                            csum[n][0] += e0 + e2;
                            csum[n][1] += e1 + e3;
                            aaS[sub][mt][n >> 1][(n & 1) * 2 + 0] = packh(e0, e1);
                            aaS[sub][mt][n >> 1][(n & 1) * 2 + 1] = packh(e2, e3);
                        }
                    }
                }
            }
            #pragma unroll
            for (int n = 0; n < 4; n++)
                #pragma unroll
                for (int p = 0; p < 2; p++) {
                    float v = csum[n][p];
                    v += __shfl_xor_sync(0xffffffffu, v, 4);
                    v += __shfl_xor_sync(0xffffffffu, v, 8);
                    v += __shfl_xor_sync(0xffffffffu, v, 16);
                    csum[n][p] = v;
                }
            if (g == 0) {
                #pragma unroll
                for (int n = 0; n < 4; n++)
                    *(float2*)&sSum[w * 64 + sub * 32 + n * 8 + tig * 2] =
                        make_float2(csum[n][0], csum[n][1]);
            }
        }
        __syncthreads();
        if (t < 64) {
            float l = 0.0f;
            #pragma unroll
            for (int w2 = 0; w2 < 16; w2++) l += sSum[w2 * 64 + t];
            lSc[t] = 1.0f / l;
        }
        __syncthreads();

        // ---------- O-mma for both subs ----------
        #pragma unroll
        for (int sub = 0; sub < 2; sub++) {
            const int qc = sub * 32;
            const int qbase = qt * 64 + qc;
            const bool liveA = (rowA <= qbase + 31);
            const bool liveB = (rowB <= qbase + 31);
            if (!liveA && !liveB) continue;
            #pragma unroll
            for (int kc = 0; kc < 2; kc++) {
                const float2 rrA = *(const float2*)&lSc[qc + kc * 16 + tig * 2];
                const float2 rrB = *(const float2*)&lSc[qc + kc * 16 + 8 + tig * 2];
                const unsigned hA = packh(rrA.x, rrA.y);
                const unsigned hB = packh(rrB.x, rrB.y);
                unsigned aa[2][4];
                #pragma unroll
                for (int mt = 0; mt < 2; mt++) {
                    aa[mt][0] = hmul2u(aaS[sub][mt][kc][0], hA);
                    aa[mt][1] = hmul2u(aaS[sub][mt][kc][1], hA);
                    aa[mt][2] = hmul2u(aaS[sub][mt][kc][2], hB);
                    aa[mt][3] = hmul2u(aaS[sub][mt][kc][3], hB);
                }
                #pragma unroll
                for (int dd = 0; dd < 3; dd++) {
                    unsigned b4[4];
                    ldsm4t(b4, vsB + (uint32_t)((qc + kc * 16) * RP + dd * 16 + tSel) * 2);
                    if (liveA) {
                        mma_f16(oacc[0][dd * 2 + 0], aa[0], b4);
                        mma_f16(oacc[0][dd * 2 + 1], aa[0], b4 + 2);
                    }
                    if (liveB) {
                        mma_f16(oacc[1][dd * 2 + 0], aa[1], b4);
                        mma_f16(oacc[1][dd * 2 + 1], aa[1], b4 + 2);
                    }
                }
            }
        }
    }

    #pragma unroll
    for (int mt = 0; mt < 2; mt++) {
        const int kg0 = (mt == 0 ? rowA : rowB) + g, kg1 = kg0 + 8;
        const float f0 = (kg0 < qlen) ? 1.0f : 0.0f;
        const float f1 = (kg1 < qlen) ? 1.0f : 0.0f;
        #pragma unroll
        for (int nd = 0; nd < 6; nd++) {
            const int col = h * DHH + nd * 8 + tig * 2;
            *(float2*)(Out + (size_t)(b * LL + kg0) * DOUTC + col) =
                make_float2(oacc[mt][nd][0] * f0, oacc[mt][nd][1] * f0);
            *(float2*)(Out + (size_t)(b * LL + kg1) * DOUTC + col) =
                make_float2(oacc[mt][nd][2] * f1, oacc[mt][nd][3] * f1);
        }
    }
}

// ---------------------------------------------------------------------------
extern "C" void kernel_launch(void* const* d_in, const int* in_sizes, int n_in,
                              void* d_out, int out_size) {
    const float* Qseq = (const float*)d_in[0];
    const float* Kseq = (const float*)d_in[1];
    const float* Vseq = (const float*)d_in[2];
    const float* WQ   = (const float*)d_in[3];
    const float* WK   = (const float*)d_in[4];
    const float* WV   = (const float*)d_in[5];
    const int*   Qlen = (const int*)d_in[6];
    const int*   Vlen = (const int*)d_in[7];

    __half *x16, *w16, *p16;
    cudaGetSymbolAddress((void**)&x16, g_x16);
    cudaGetSymbolAddress((void**)&w16, g_w16);
    cudaGetSymbolAddress((void**)&p16, g_p16);

    cudaFuncSetAttribute(attn_fused, cudaFuncAttributeMaxDynamicSharedMemorySize, SMEM_ATT);

    conv_f2h<<<dim3(2048, 3), 256>>>(Qseq, Kseq, Vseq, x16,
                                     (size_t)M_TOT * DIN, M_TOT * DIN / 4);
    conv_f2h<<<dim3(576, 3), 256>>>(WQ, WK, WV, w16,
                                    (size_t)DIN * DOUTC, DIN * DOUTC / 4);

    proj16<<<dim3(6, 128, 3), 256>>>(x16, w16, p16);

    attn_fused<<<BB * HH, 512, SMEM_ATT>>>(p16, Qlen, Vlen, (float*)d_out);
}